// round 8
// baseline (speedup 1.0000x reference)
#include <cuda_runtime.h>
#include <math.h>

#define H 1024
#define E 1024
#define L 2048
#define HE 2048
#define H3 3072
#define NB 444                   // 3 blocks per SM on 148 SMs (co-resident)
#define TPB 256
#define NTHREADS (NB * TPB)      // 113664
#define NWARPS (NTHREADS / 32)   // 3552

// ---------------- scratch (__device__ globals; no allocation) ----------------
__device__ __align__(16) float g_d[E];
__device__ __align__(16) float g_x[HE];              // [g ; c]
__device__ __align__(16) float g_part[16 * L];
__device__ __align__(16) float g_attn[L];
__device__ __align__(16) float g_gx[H3];
__device__ __align__(16) float g_gh[H3];
__device__ float g_sum;
__device__ unsigned g_bar = 0;   // [epoch:12 | count:20] packed grid barrier

// ---------------- helpers ----------------
__device__ __forceinline__ float warp_sum(float v) {
    #pragma unroll
    for (int o = 16; o; o >>= 1) v += __shfl_down_sync(0xffffffffu, v, o);
    return v;
}
__device__ __forceinline__ float warp_max(float v) {
    #pragma unroll
    for (int o = 16; o; o >>= 1) v = fmaxf(v, __shfl_down_sync(0xffffffffu, v, o));
    return v;
}
__device__ __forceinline__ float dot4(const float4 a, const float4 b) {
    return a.x * b.x + a.y * b.y + a.z * b.z + a.w * b.w;
}
__device__ __forceinline__ float sigmoidf(float x) { return 1.0f / (1.0f + expf(-x)); }

// Grid-wide barrier. Arrival: one atomicAdd per block (RMW). Wait: plain
// volatile LOADS — no RMW serialization at the LTS, release propagates at
// L2 read latency. Epoch in bits[20:32) wraps cleanly through 2^32.
__device__ __forceinline__ void grid_bar() {
    __syncthreads();
    if (threadIdx.x == 0) {
        __threadfence();
        unsigned old = atomicAdd(&g_bar, 1u);
        unsigned epoch = old >> 20;
        if ((old & 0xFFFFFu) == NB - 1u) {
            atomicAdd(&g_bar, (1u << 20) - (unsigned)NB);  // drain count, bump epoch
        } else {
            volatile unsigned* vb = &g_bar;
            while ((*vb >> 20) == epoch) __nanosleep(32);
        }
        __threadfence();
    }
    __syncthreads();
}

// warp-cooperative dot over 1024 floats: 8+8 batched LDG.128
__device__ __forceinline__ float wdot1024(const float* __restrict__ row,
                                          const float* __restrict__ vec, int lane) {
    const float4* r4 = reinterpret_cast<const float4*>(row);
    const float4* v4 = reinterpret_cast<const float4*>(vec);
    float4 w[8], x[8];
    #pragma unroll
    for (int k = 0; k < 8; k++) w[k] = r4[lane + 32 * k];
    #pragma unroll
    for (int k = 0; k < 8; k++) x[k] = v4[lane + 32 * k];
    float a0 = 0.f, a1 = 0.f;
    #pragma unroll
    for (int k = 0; k < 8; k += 2) { a0 += dot4(w[k], x[k]); a1 += dot4(w[k+1], x[k+1]); }
    return a0 + a1;  // caller warp-reduces
}
__device__ __forceinline__ float wdot2048(const float* __restrict__ row,
                                          const float* __restrict__ vec, int lane) {
    return wdot1024(row, vec, lane) + wdot1024(row + 1024, vec + 1024, lane);
}

// ================= the whole decoder in one persistent kernel =================
__global__ __launch_bounds__(TPB, 3) void fused_decoder(
        const int* __restrict__ y, const float* __restrict__ h,
        const float* __restrict__ cnn_a, const float* __restrict__ cnn_c,
        const float* __restrict__ emb,
        const float* __restrict__ W_t, const float* __restrict__ b_t,
        const float* __restrict__ W_ih, const float* __restrict__ W_hh,
        const float* __restrict__ b_ih, const float* __restrict__ b_hh,
        const float* __restrict__ W_o, const float* __restrict__ b_o,
        float* __restrict__ out_logits, float* __restrict__ out_hidden, int V) {
    __shared__ float4 sh[H / 4];                         // h_new staged per block (4 KB)
    const int lane = threadIdx.x & 31;
    const int gw   = (blockIdx.x * TPB + threadIdx.x) >> 5;  // global warp id
    const int gt   = blockIdx.x * TPB + threadIdx.x;         // global thread id

    // ---- S1: d[e] = W_t[e,:]·h + b_t[e] + g[e]; x[e] = g[e]; zero g_sum ----
    if (gt == 0) g_sum = 0.f;
    for (int e = gw; e < E; e += NWARPS) {
        float acc = warp_sum(wdot1024(W_t + (size_t)e * H, h, lane));
        if (lane == 0) {
            float g = emb[(size_t)y[0] * H + e];
            g_d[e] = acc + b_t[e] + g;
            g_x[e] = g;
        }
    }
    grid_bar();

    // ---- S2 (parallel): scores partials | gh = W_hh·h + b_hh | gx = W_ih[:, :H]·g + b_ih ----
    for (int t = gw; t < 1024 + H3 + H3; t += NWARPS) {
        if (t < 1024) {
            int p = t >> 6, lw = t & 63;
            int l = lw * 32 + lane;
            const float* __restrict__ col = cnn_a + (size_t)(p * 64) * L + l;
            const float* __restrict__ dd  = g_d + p * 64;
            float a0 = 0.f, a1 = 0.f, a2 = 0.f, a3 = 0.f;
            #pragma unroll
            for (int e = 0; e < 64; e += 4) {
                a0 += dd[e]     * col[(size_t)e * L];
                a1 += dd[e + 1] * col[(size_t)(e + 1) * L];
                a2 += dd[e + 2] * col[(size_t)(e + 2) * L];
                a3 += dd[e + 3] * col[(size_t)(e + 3) * L];
            }
            g_part[p * L + l] = (a0 + a1) + (a2 + a3);
        } else if (t < 1024 + H3) {
            int j = t - 1024;
            float acc = warp_sum(wdot1024(W_hh + (size_t)j * H, h, lane));
            if (lane == 0) g_gh[j] = acc + b_hh[j];
        } else {
            int j = t - 1024 - H3;
            float acc = warp_sum(wdot1024(W_ih + (size_t)j * HE, g_x, lane));
            if (lane == 0) g_gx[j] = acc + b_ih[j];
        }
    }
    grid_bar();

    // ---- S3: softmax over L (block 0 only) ----
    if (blockIdx.x == 0) {
        __shared__ float red[8];
        __shared__ float bval;
        int tt = threadIdx.x;
        float v[8];
        float m = -INFINITY;
        #pragma unroll
        for (int j = 0; j < 8; j++) {
            int l = tt + 256 * j;
            float s = 0.f;
            #pragma unroll
            for (int p = 0; p < 16; p++) s += g_part[p * L + l];
            v[j] = s;
            m = fmaxf(m, s);
        }
        m = warp_max(m);
        if (lane == 0) red[tt >> 5] = m;
        __syncthreads();
        if (tt == 0) {
            float mm = red[0];
            #pragma unroll
            for (int i = 1; i < 8; i++) mm = fmaxf(mm, red[i]);
            bval = mm;
        }
        __syncthreads();
        float M = bval;
        float s = 0.f;
        #pragma unroll
        for (int j = 0; j < 8; j++) { v[j] = expf(v[j] - M); s += v[j]; }
        s = warp_sum(s);
        __syncthreads();
        if (lane == 0) red[tt >> 5] = s;
        __syncthreads();
        if (tt == 0) {
            float ss = 0.f;
            #pragma unroll
            for (int i = 0; i < 8; i++) ss += red[i];
            bval = ss;
        }
        __syncthreads();
        float inv = 1.0f / bval;
        #pragma unroll
        for (int j = 0; j < 8; j++) g_attn[tt + 256 * j] = v[j] * inv;
    }
    grid_bar();

    // ---- S4: c[r] = attn · cnn_c[r,:] ----
    for (int r = gw; r < H; r += NWARPS) {
        float acc = warp_sum(wdot2048(cnn_c + (size_t)r * L, g_attn, lane));
        if (lane == 0) g_x[H + r] = acc;
    }
    grid_bar();

    // ---- S5: gx[r] += W_ih[r, H:]·c ----
    for (int r = gw; r < H3; r += NWARPS) {
        float acc = warp_sum(wdot1024(W_ih + (size_t)r * HE + 1024, g_x + 1024, lane));
        if (lane == 0) g_gx[r] += acc;
    }
    grid_bar();

    // ---- S6 (inlined per block, redundant): GRU combine -> h_new in SMEM ----
    {
        int t = threadIdx.x;                       // element group 4t..4t+3
        const float4* gx4 = reinterpret_cast<const float4*>(g_gx);
        const float4* gh4 = reinterpret_cast<const float4*>(g_gh);
        const float4* h4  = reinterpret_cast<const float4*>(h);
        float4 ra = gx4[t],        rb = gh4[t];
        float4 za = gx4[256 + t],  zb = gh4[256 + t];
        float4 na = gx4[512 + t],  nb = gh4[512 + t];
        float4 hh = h4[t];
        float4 hn;
        {
            float r0 = sigmoidf(ra.x + rb.x), z0 = sigmoidf(za.x + zb.x);
            float n0 = tanhf(na.x + r0 * nb.x);
            hn.x = (1.f - z0) * n0 + z0 * hh.x;
            float r1 = sigmoidf(ra.y + rb.y), z1 = sigmoidf(za.y + zb.y);
            float n1 = tanhf(na.y + r1 * nb.y);
            hn.y = (1.f - z1) * n1 + z1 * hh.y;
            float r2 = sigmoidf(ra.z + rb.z), z2 = sigmoidf(za.z + zb.z);
            float n2 = tanhf(na.z + r2 * nb.z);
            hn.z = (1.f - z2) * n2 + z2 * hh.z;
            float r3 = sigmoidf(ra.w + rb.w), z3 = sigmoidf(za.w + zb.w);
            float n3 = tanhf(na.w + r3 * nb.w);
            hn.w = (1.f - z3) * n3 + z3 * hh.w;
        }
        sh[t] = hn;
        if (blockIdx.x == 0) {
            // out_hidden is only 4-byte aligned (offset V into d_out) -> scalar stores
            out_hidden[4 * t + 0] = hn.x;
            out_hidden[4 * t + 1] = hn.y;
            out_hidden[4 * t + 2] = hn.z;
            out_hidden[4 * t + 3] = hn.w;
        }
        __syncthreads();
    }

    // ---- S7: logits = W_o·h_new + b_o + fused exp-sum (h_new from SMEM) ----
    {
        float esum = 0.f;
        for (int v = gw; v < V; v += NWARPS) {
            const float4* w4 = reinterpret_cast<const float4*>(W_o + (size_t)v * H);
            float4 wv[8];
            #pragma unroll
            for (int k = 0; k < 8; k++) wv[k] = w4[lane + 32 * k];
            float a0 = 0.f, a1 = 0.f;
            #pragma unroll
            for (int k = 0; k < 8; k += 2) {
                a0 += dot4(wv[k],     sh[lane + 32 * k]);
                a1 += dot4(wv[k + 1], sh[lane + 32 * (k + 1)]);
            }
            float d = warp_sum(a0 + a1);
            if (lane == 0) {
                float lg = d + b_o[v];
                out_logits[v] = lg;
                esum += expf(lg);
            }
        }
        if (lane == 0) atomicAdd(&g_sum, esum);
    }
    grid_bar();

    // ---- S8: out[v] -= log(sum_exp) ----
    {
        float lse = logf(g_sum);
        for (int v = gt; v < V; v += NTHREADS) out_logits[v] -= lse;
    }
}

// ---------------- launch ----------------
extern "C" void kernel_launch(void* const* d_in, const int* in_sizes, int n_in,
                              void* d_out, int out_size) {
    const int*   y_i   = (const int*)  d_in[0];
    const float* h_i   = (const float*)d_in[1];
    const float* cnn_a = (const float*)d_in[2];
    const float* cnn_c = (const float*)d_in[3];
    const float* emb   = (const float*)d_in[4];
    const float* W_t   = (const float*)d_in[5];
    const float* b_t   = (const float*)d_in[6];
    const float* W_ih  = (const float*)d_in[7];
    const float* W_hh  = (const float*)d_in[8];
    const float* b_ih  = (const float*)d_in[9];
    const float* b_hh  = (const float*)d_in[10];
    const float* W_o   = (const float*)d_in[11];
    const float* b_o   = (const float*)d_in[12];

    const int V = in_sizes[11] / H;           // 50257
    float* out        = (float*)d_out;
    float* out_logits = out;
    float* out_hidden = out + (out_size - H);

    fused_decoder<<<NB, TPB>>>(y_i, h_i, cnn_a, cnn_c, emb, W_t, b_t,
                               W_ih, W_hh, b_ih, b_hh, W_o, b_o,
                               out_logits, out_hidden, V);
}

// round 9
// speedup vs baseline: 1.0136x; 1.0136x over previous
#include <cuda_runtime.h>
#include <math.h>

#define H 1024
#define E 1024
#define L 2048
#define HE 2048
#define H3 3072
#define NB 444                   // 3 blocks per SM on 148 SMs (co-resident)
#define TPB 256
#define NTHREADS (NB * TPB)      // 113664
#define NWARPS (NTHREADS / 32)   // 3552
#define CRIT 128                 // critical-path blocks
#define CWARPS (CRIT * TPB / 32) // 1024
#define OWARPS (NWARPS - CWARPS) // 2528

// ---------------- scratch (__device__ globals; no allocation) ----------------
__device__ __align__(16) float g_d[E];
__device__ __align__(16) float g_c[H];               // context vector
__device__ __align__(16) float g_part[16 * L];
__device__ __align__(16) float g_attn[L];
__device__ __align__(16) float g_gx[H3];             // b_ih + W_ih[:, :H]·g   (off-path)
__device__ __align__(16) float g_gx2[H3];            // W_ih[:, H:]·c          (crit S5)
__device__ __align__(16) float g_gh[H3];             // b_hh + W_hh·h          (off-path)
__device__ float g_sum;
__device__ unsigned g_bar  = 0;  // full-grid barrier word
__device__ unsigned g_barc = 0;  // critical-group barrier word

// ---------------- helpers ----------------
__device__ __forceinline__ float warp_sum(float v) {
    #pragma unroll
    for (int o = 16; o; o >>= 1) v += __shfl_down_sync(0xffffffffu, v, o);
    return v;
}
__device__ __forceinline__ float warp_max(float v) {
    #pragma unroll
    for (int o = 16; o; o >>= 1) v = fmaxf(v, __shfl_down_sync(0xffffffffu, v, o));
    return v;
}
__device__ __forceinline__ float dot4(const float4 a, const float4 b) {
    return a.x * b.x + a.y * b.y + a.z * b.z + a.w * b.w;
}
__device__ __forceinline__ float sigmoidf(float x) { return 1.0f / (1.0f + expf(-x)); }

// Packed-word barrier: count in bits[0:20), epoch in bits[20:32).
__device__ __forceinline__ void barrier_on(unsigned* word, unsigned count) {
    __syncthreads();
    if (threadIdx.x == 0) {
        __threadfence();
        unsigned old = atomicAdd(word, 1u);
        unsigned epoch = old >> 20;
        if ((old & 0xFFFFFu) == count - 1u) {
            atomicAdd(word, (1u << 20) - count);   // drain count, bump epoch
        } else {
            volatile unsigned* vb = word;
            while ((*vb >> 20) == epoch) __nanosleep(32);
        }
        __threadfence();
    }
    __syncthreads();
}
__device__ __forceinline__ void full_bar() { barrier_on(&g_bar,  NB); }
__device__ __forceinline__ void crit_bar() { barrier_on(&g_barc, CRIT); }

// warp-cooperative dot over 1024 floats: 8+8 batched LDG.128
__device__ __forceinline__ float wdot1024(const float* __restrict__ row,
                                          const float* __restrict__ vec, int lane) {
    const float4* r4 = reinterpret_cast<const float4*>(row);
    const float4* v4 = reinterpret_cast<const float4*>(vec);
    float4 w[8], x[8];
    #pragma unroll
    for (int k = 0; k < 8; k++) w[k] = r4[lane + 32 * k];
    #pragma unroll
    for (int k = 0; k < 8; k++) x[k] = v4[lane + 32 * k];
    float a0 = 0.f, a1 = 0.f;
    #pragma unroll
    for (int k = 0; k < 8; k += 2) { a0 += dot4(w[k], x[k]); a1 += dot4(w[k+1], x[k+1]); }
    return a0 + a1;  // caller warp-reduces
}
__device__ __forceinline__ float wdot2048(const float* __restrict__ row,
                                          const float* __restrict__ vec, int lane) {
    return wdot1024(row, vec, lane) + wdot1024(row + 1024, vec + 1024, lane);
}

// ================= the whole decoder in one persistent kernel =================
__global__ __launch_bounds__(TPB, 3) void fused_decoder(
        const int* __restrict__ y, const float* __restrict__ h,
        const float* __restrict__ cnn_a, const float* __restrict__ cnn_c,
        const float* __restrict__ emb,
        const float* __restrict__ W_t, const float* __restrict__ b_t,
        const float* __restrict__ W_ih, const float* __restrict__ W_hh,
        const float* __restrict__ b_ih, const float* __restrict__ b_hh,
        const float* __restrict__ W_o, const float* __restrict__ b_o,
        float* __restrict__ out_logits, float* __restrict__ out_hidden, int V) {
    __shared__ float4 sh[H / 4];                         // h_new staged per block (4 KB)
    const int lane = threadIdx.x & 31;
    const int gw   = (blockIdx.x * TPB + threadIdx.x) >> 5;  // global warp id
    const int gt   = blockIdx.x * TPB + threadIdx.x;         // global thread id

    if (blockIdx.x < CRIT) {
        // =============== CRITICAL-PATH GROUP (1024 warps) ===============
        const int cw = gw;                               // 0..1023

        // ---- S1: d[e] = W_t[e,:]·h + b_t[e] + emb[y,e]  (1 round) ----
        if (gt == 0) g_sum = 0.f;
        {
            float acc = warp_sum(wdot1024(W_t + (size_t)cw * H, h, lane));
            if (lane == 0)
                g_d[cw] = acc + b_t[cw] + emb[(size_t)y[0] * H + cw];
        }
        crit_bar();

        // ---- S2c: scores partials (1024 tasks, 1 round) ----
        {
            int p = cw >> 6, lw = cw & 63;
            int l = lw * 32 + lane;
            const float* __restrict__ col = cnn_a + (size_t)(p * 64) * L + l;
            const float* __restrict__ dd  = g_d + p * 64;
            float a0 = 0.f, a1 = 0.f, a2 = 0.f, a3 = 0.f;
            #pragma unroll
            for (int e = 0; e < 64; e += 4) {
                a0 += dd[e]     * col[(size_t)e * L];
                a1 += dd[e + 1] * col[(size_t)(e + 1) * L];
                a2 += dd[e + 2] * col[(size_t)(e + 2) * L];
                a3 += dd[e + 3] * col[(size_t)(e + 3) * L];
            }
            g_part[p * L + l] = (a0 + a1) + (a2 + a3);
        }
        crit_bar();

        // ---- S3: softmax over L (block 0 only) ----
        if (blockIdx.x == 0) {
            __shared__ float red[8];
            __shared__ float bval;
            int tt = threadIdx.x;
            float v[8];
            float m = -INFINITY;
            #pragma unroll
            for (int j = 0; j < 8; j++) {
                int l = tt + 256 * j;
                float s = 0.f;
                #pragma unroll
                for (int p = 0; p < 16; p++) s += g_part[p * L + l];
                v[j] = s;
                m = fmaxf(m, s);
            }
            m = warp_max(m);
            if (lane == 0) red[tt >> 5] = m;
            __syncthreads();
            if (tt == 0) {
                float mm = red[0];
                #pragma unroll
                for (int i = 1; i < 8; i++) mm = fmaxf(mm, red[i]);
                bval = mm;
            }
            __syncthreads();
            float M = bval;
            float s = 0.f;
            #pragma unroll
            for (int j = 0; j < 8; j++) { v[j] = expf(v[j] - M); s += v[j]; }
            s = warp_sum(s);
            __syncthreads();
            if (lane == 0) red[tt >> 5] = s;
            __syncthreads();
            if (tt == 0) {
                float ss = 0.f;
                #pragma unroll
                for (int i = 0; i < 8; i++) ss += red[i];
                bval = ss;
            }
            __syncthreads();
            float inv = 1.0f / bval;
            #pragma unroll
            for (int j = 0; j < 8; j++) g_attn[tt + 256 * j] = v[j] * inv;
        }
        crit_bar();

        // ---- S4: c[r] = attn · cnn_c[r,:]  (1 round) ----
        {
            float acc = warp_sum(wdot2048(cnn_c + (size_t)cw * L, g_attn, lane));
            if (lane == 0) g_c[cw] = acc;
        }
        crit_bar();

        // ---- S5: gx2[r] = W_ih[r, H:]·c  (3 rounds) ----
        for (int r = cw; r < H3; r += CWARPS) {
            float acc = warp_sum(wdot1024(W_ih + (size_t)r * HE + 1024, g_c, lane));
            if (lane == 0) g_gx2[r] = acc;
        }
    } else {
        // =============== OFF-PATH GROUP (2528 warps), no dependencies ===============
        // gh[j] = W_hh[j,:]·h + b_hh[j];  gx[j] = W_ih[j, :H]·g + b_ih[j], g from emb.
        const int ow = gw - CWARPS;                       // 0..2527
        const float* __restrict__ grow = emb + (size_t)y[0] * H;
        for (int j = ow; j < 2 * H3; j += OWARPS) {
            if (j < H3) {
                float acc = warp_sum(wdot1024(W_hh + (size_t)j * H, h, lane));
                if (lane == 0) g_gh[j] = acc + b_hh[j];
            } else {
                int jj = j - H3;
                float acc = warp_sum(wdot1024(W_ih + (size_t)jj * HE, grow, lane));
                if (lane == 0) g_gx[jj] = acc + b_ih[jj];
            }
        }
    }
    full_bar();

    // ---- S6 (inlined per block, redundant): GRU combine -> h_new in SMEM ----
    {
        int t = threadIdx.x;                       // element group 4t..4t+3
        const float4* gx4  = reinterpret_cast<const float4*>(g_gx);
        const float4* gx24 = reinterpret_cast<const float4*>(g_gx2);
        const float4* gh4  = reinterpret_cast<const float4*>(g_gh);
        const float4* h4   = reinterpret_cast<const float4*>(h);
        float4 ra = gx4[t],       ra2 = gx24[t],       rb = gh4[t];
        float4 za = gx4[256 + t], za2 = gx24[256 + t], zb = gh4[256 + t];
        float4 na = gx4[512 + t], na2 = gx24[512 + t], nb = gh4[512 + t];
        float4 hh = h4[t];
        float4 hn;
        {
            float r0 = sigmoidf(ra.x + ra2.x + rb.x), z0 = sigmoidf(za.x + za2.x + zb.x);
            float n0 = tanhf(na.x + na2.x + r0 * nb.x);
            hn.x = (1.f - z0) * n0 + z0 * hh.x;
            float r1 = sigmoidf(ra.y + ra2.y + rb.y), z1 = sigmoidf(za.y + za2.y + zb.y);
            float n1 = tanhf(na.y + na2.y + r1 * nb.y);
            hn.y = (1.f - z1) * n1 + z1 * hh.y;
            float r2 = sigmoidf(ra.z + ra2.z + rb.z), z2 = sigmoidf(za.z + za2.z + zb.z);
            float n2 = tanhf(na.z + na2.z + r2 * nb.z);
            hn.z = (1.f - z2) * n2 + z2 * hh.z;
            float r3 = sigmoidf(ra.w + ra2.w + rb.w), z3 = sigmoidf(za.w + za2.w + zb.w);
            float n3 = tanhf(na.w + na2.w + r3 * nb.w);
            hn.w = (1.f - z3) * n3 + z3 * hh.w;
        }
        sh[t] = hn;
        if (blockIdx.x == 0) {
            // out_hidden is only 4-byte aligned (offset V into d_out) -> scalar stores
            out_hidden[4 * t + 0] = hn.x;
            out_hidden[4 * t + 1] = hn.y;
            out_hidden[4 * t + 2] = hn.z;
            out_hidden[4 * t + 3] = hn.w;
        }
        __syncthreads();
    }

    // ---- S7: logits = W_o·h_new + b_o + fused exp-sum (h_new from SMEM) ----
    {
        float esum = 0.f;
        for (int v = gw; v < V; v += NWARPS) {
            float bo = b_o[v];                           // prefetch, overlaps weight loads
            const float4* w4 = reinterpret_cast<const float4*>(W_o + (size_t)v * H);
            float4 wv[8];
            #pragma unroll
            for (int k = 0; k < 8; k++) wv[k] = w4[lane + 32 * k];
            float a0 = 0.f, a1 = 0.f;
            #pragma unroll
            for (int k = 0; k < 8; k += 2) {
                a0 += dot4(wv[k],     sh[lane + 32 * k]);
                a1 += dot4(wv[k + 1], sh[lane + 32 * (k + 1)]);
            }
            float d = warp_sum(a0 + a1);
            if (lane == 0) {
                float lg = d + bo;
                out_logits[v] = lg;
                esum += expf(lg);
            }
        }
        if (lane == 0) atomicAdd(&g_sum, esum);
    }
    full_bar();

    // ---- S8: out[v] -= log(sum_exp) ----
    {
        float lse = logf(g_sum);
        for (int v = gt; v < V; v += NTHREADS) out_logits[v] -= lse;
    }
}

// ---------------- launch ----------------
extern "C" void kernel_launch(void* const* d_in, const int* in_sizes, int n_in,
                              void* d_out, int out_size) {
    const int*   y_i   = (const int*)  d_in[0];
    const float* h_i   = (const float*)d_in[1];
    const float* cnn_a = (const float*)d_in[2];
    const float* cnn_c = (const float*)d_in[3];
    const float* emb   = (const float*)d_in[4];
    const float* W_t   = (const float*)d_in[5];
    const float* b_t   = (const float*)d_in[6];
    const float* W_ih  = (const float*)d_in[7];
    const float* W_hh  = (const float*)d_in[8];
    const float* b_ih  = (const float*)d_in[9];
    const float* b_hh  = (const float*)d_in[10];
    const float* W_o   = (const float*)d_in[11];
    const float* b_o   = (const float*)d_in[12];

    const int V = in_sizes[11] / H;           // 50257
    float* out        = (float*)d_out;
    float* out_logits = out;
    float* out_hidden = out + (out_size - H);

    fused_decoder<<<NB, TPB>>>(y_i, h_i, cnn_a, cnn_c, emb, W_t, b_t,
                               W_ih, W_hh, b_ih, b_hh, W_o, b_o,
                               out_logits, out_hidden, V);
}

// round 10
// speedup vs baseline: 1.0448x; 1.0307x over previous
#include <cuda_runtime.h>
#include <math.h>

#define H 1024
#define E 1024
#define L 2048
#define HE 2048
#define H3 3072
#define NB 296                   // 2 blocks per SM (128-reg budget for pipelined S7)
#define TPB 256
#define NTHREADS (NB * TPB)      // 75776
#define NWARPS (NTHREADS / 32)   // 2368
#define CRIT 128                 // critical-path blocks
#define CWARPS (CRIT * TPB / 32) // 1024
#define OWARPS (NWARPS - CWARPS) // 1344

// ---------------- scratch (__device__ globals; no allocation) ----------------
__device__ __align__(16) float g_d[E];
__device__ __align__(16) float g_c[H];               // context vector
__device__ __align__(16) float g_part[16 * L];
__device__ __align__(16) float g_attn[L];
__device__ __align__(16) float g_gx[H3];             // b_ih + W_ih[:, :H]·g   (off-path)
__device__ __align__(16) float g_gx2[H3];            // W_ih[:, H:]·c          (crit S5)
__device__ __align__(16) float g_gh[H3];             // b_hh + W_hh·h          (off-path)
__device__ float g_sum;
__device__ unsigned g_bar  = 0;  // full-grid barrier word
__device__ unsigned g_barc = 0;  // critical-group barrier word

// ---------------- helpers ----------------
__device__ __forceinline__ float warp_sum(float v) {
    #pragma unroll
    for (int o = 16; o; o >>= 1) v += __shfl_down_sync(0xffffffffu, v, o);
    return v;
}
__device__ __forceinline__ float warp_max(float v) {
    #pragma unroll
    for (int o = 16; o; o >>= 1) v = fmaxf(v, __shfl_down_sync(0xffffffffu, v, o));
    return v;
}
__device__ __forceinline__ float dot4(const float4 a, const float4 b) {
    return a.x * b.x + a.y * b.y + a.z * b.z + a.w * b.w;
}
__device__ __forceinline__ float sigmoidf(float x) { return 1.0f / (1.0f + expf(-x)); }

// Packed-word barrier: count in bits[0:20), epoch in bits[20:32).
__device__ __forceinline__ void barrier_on(unsigned* word, unsigned count) {
    __syncthreads();
    if (threadIdx.x == 0) {
        __threadfence();
        unsigned old = atomicAdd(word, 1u);
        unsigned epoch = old >> 20;
        if ((old & 0xFFFFFu) == count - 1u) {
            atomicAdd(word, (1u << 20) - count);   // drain count, bump epoch
        } else {
            volatile unsigned* vb = word;
            while ((*vb >> 20) == epoch) __nanosleep(32);
        }
        __threadfence();
    }
    __syncthreads();
}
__device__ __forceinline__ void full_bar() { barrier_on(&g_bar,  NB); }
__device__ __forceinline__ void crit_bar() { barrier_on(&g_barc, CRIT); }

// warp-cooperative dot over 1024 floats: 8+8 batched LDG.128
__device__ __forceinline__ float wdot1024(const float* __restrict__ row,
                                          const float* __restrict__ vec, int lane) {
    const float4* r4 = reinterpret_cast<const float4*>(row);
    const float4* v4 = reinterpret_cast<const float4*>(vec);
    float4 w[8], x[8];
    #pragma unroll
    for (int k = 0; k < 8; k++) w[k] = r4[lane + 32 * k];
    #pragma unroll
    for (int k = 0; k < 8; k++) x[k] = v4[lane + 32 * k];
    float a0 = 0.f, a1 = 0.f;
    #pragma unroll
    for (int k = 0; k < 8; k += 2) { a0 += dot4(w[k], x[k]); a1 += dot4(w[k+1], x[k+1]); }
    return a0 + a1;  // caller warp-reduces
}
__device__ __forceinline__ float wdot2048(const float* __restrict__ row,
                                          const float* __restrict__ vec, int lane) {
    return wdot1024(row, vec, lane) + wdot1024(row + 1024, vec + 1024, lane);
}

// ================= the whole decoder in one persistent kernel =================
__global__ __launch_bounds__(TPB, 2) void fused_decoder(
        const int* __restrict__ y, const float* __restrict__ h,
        const float* __restrict__ cnn_a, const float* __restrict__ cnn_c,
        const float* __restrict__ emb,
        const float* __restrict__ W_t, const float* __restrict__ b_t,
        const float* __restrict__ W_ih, const float* __restrict__ W_hh,
        const float* __restrict__ b_ih, const float* __restrict__ b_hh,
        const float* __restrict__ W_o, const float* __restrict__ b_o,
        float* __restrict__ out_logits, float* __restrict__ out_hidden, int V) {
    __shared__ float4 sh[H / 4];                         // h_new staged per block (4 KB)
    const int lane = threadIdx.x & 31;
    const int gw   = (blockIdx.x * TPB + threadIdx.x) >> 5;  // global warp id
    const int gt   = blockIdx.x * TPB + threadIdx.x;         // global thread id

    if (blockIdx.x < CRIT) {
        // =============== CRITICAL-PATH GROUP (1024 warps) ===============
        const int cw = gw;                               // 0..1023

        // ---- S1: d[e] = W_t[e,:]·h + b_t[e] + emb[y,e]  (1 round) ----
        if (gt == 0) g_sum = 0.f;
        {
            float acc = warp_sum(wdot1024(W_t + (size_t)cw * H, h, lane));
            if (lane == 0)
                g_d[cw] = acc + b_t[cw] + emb[(size_t)y[0] * H + cw];
        }
        crit_bar();

        // ---- S2c: scores partials (1024 tasks, 1 round) ----
        {
            int p = cw >> 6, lw = cw & 63;
            int l = lw * 32 + lane;
            const float* __restrict__ col = cnn_a + (size_t)(p * 64) * L + l;
            const float* __restrict__ dd  = g_d + p * 64;
            float a0 = 0.f, a1 = 0.f, a2 = 0.f, a3 = 0.f;
            #pragma unroll
            for (int e = 0; e < 64; e += 4) {
                a0 += dd[e]     * col[(size_t)e * L];
                a1 += dd[e + 1] * col[(size_t)(e + 1) * L];
                a2 += dd[e + 2] * col[(size_t)(e + 2) * L];
                a3 += dd[e + 3] * col[(size_t)(e + 3) * L];
            }
            g_part[p * L + l] = (a0 + a1) + (a2 + a3);
        }
        crit_bar();

        // ---- S3: softmax over L (block 0 only) ----
        if (blockIdx.x == 0) {
            __shared__ float red[8];
            __shared__ float bval;
            int tt = threadIdx.x;
            float v[8];
            float m = -INFINITY;
            #pragma unroll
            for (int j = 0; j < 8; j++) {
                int l = tt + 256 * j;
                float s = 0.f;
                #pragma unroll
                for (int p = 0; p < 16; p++) s += g_part[p * L + l];
                v[j] = s;
                m = fmaxf(m, s);
            }
            m = warp_max(m);
            if (lane == 0) red[tt >> 5] = m;
            __syncthreads();
            if (tt == 0) {
                float mm = red[0];
                #pragma unroll
                for (int i = 1; i < 8; i++) mm = fmaxf(mm, red[i]);
                bval = mm;
            }
            __syncthreads();
            float M = bval;
            float s = 0.f;
            #pragma unroll
            for (int j = 0; j < 8; j++) { v[j] = expf(v[j] - M); s += v[j]; }
            s = warp_sum(s);
            __syncthreads();
            if (lane == 0) red[tt >> 5] = s;
            __syncthreads();
            if (tt == 0) {
                float ss = 0.f;
                #pragma unroll
                for (int i = 0; i < 8; i++) ss += red[i];
                bval = ss;
            }
            __syncthreads();
            float inv = 1.0f / bval;
            #pragma unroll
            for (int j = 0; j < 8; j++) g_attn[tt + 256 * j] = v[j] * inv;
        }
        crit_bar();

        // ---- S4: c[r] = attn · cnn_c[r,:]  (1 round) ----
        {
            float acc = warp_sum(wdot2048(cnn_c + (size_t)cw * L, g_attn, lane));
            if (lane == 0) g_c[cw] = acc;
        }
        crit_bar();

        // ---- S5: gx2[r] = W_ih[r, H:]·c  (3 rounds) ----
        for (int r = cw; r < H3; r += CWARPS) {
            float acc = warp_sum(wdot1024(W_ih + (size_t)r * HE + 1024, g_c, lane));
            if (lane == 0) g_gx2[r] = acc;
        }
    } else {
        // =============== OFF-PATH GROUP (1344 warps), no dependencies ===============
        const int ow = gw - CWARPS;
        const float* __restrict__ grow = emb + (size_t)y[0] * H;
        for (int j = ow; j < 2 * H3; j += OWARPS) {
            if (j < H3) {
                float acc = warp_sum(wdot1024(W_hh + (size_t)j * H, h, lane));
                if (lane == 0) g_gh[j] = acc + b_hh[j];
            } else {
                int jj = j - H3;
                float acc = warp_sum(wdot1024(W_ih + (size_t)jj * HE, grow, lane));
                if (lane == 0) g_gx[jj] = acc + b_ih[jj];
            }
        }
    }
    full_bar();

    // ---- S6 (inlined per block, redundant): GRU combine -> h_new in SMEM ----
    {
        int t = threadIdx.x;                       // element group 4t..4t+3
        const float4* gx4  = reinterpret_cast<const float4*>(g_gx);
        const float4* gx24 = reinterpret_cast<const float4*>(g_gx2);
        const float4* gh4  = reinterpret_cast<const float4*>(g_gh);
        const float4* h4   = reinterpret_cast<const float4*>(h);
        float4 ra = gx4[t],       ra2 = gx24[t],       rb = gh4[t];
        float4 za = gx4[256 + t], za2 = gx24[256 + t], zb = gh4[256 + t];
        float4 na = gx4[512 + t], na2 = gx24[512 + t], nb = gh4[512 + t];
        float4 hh = h4[t];
        float4 hn;
        {
            float r0 = sigmoidf(ra.x + ra2.x + rb.x), z0 = sigmoidf(za.x + za2.x + zb.x);
            float n0 = tanhf(na.x + na2.x + r0 * nb.x);
            hn.x = (1.f - z0) * n0 + z0 * hh.x;
            float r1 = sigmoidf(ra.y + ra2.y + rb.y), z1 = sigmoidf(za.y + za2.y + zb.y);
            float n1 = tanhf(na.y + na2.y + r1 * nb.y);
            hn.y = (1.f - z1) * n1 + z1 * hh.y;
            float r2 = sigmoidf(ra.z + ra2.z + rb.z), z2 = sigmoidf(za.z + za2.z + zb.z);
            float n2 = tanhf(na.z + na2.z + r2 * nb.z);
            hn.z = (1.f - z2) * n2 + z2 * hh.z;
            float r3 = sigmoidf(ra.w + ra2.w + rb.w), z3 = sigmoidf(za.w + za2.w + zb.w);
            float n3 = tanhf(na.w + na2.w + r3 * nb.w);
            hn.w = (1.f - z3) * n3 + z3 * hh.w;
        }
        sh[t] = hn;
        if (blockIdx.x == 0) {
            // out_hidden is only 4-byte aligned (offset V into d_out) -> scalar stores
            out_hidden[4 * t + 0] = hn.x;
            out_hidden[4 * t + 1] = hn.y;
            out_hidden[4 * t + 2] = hn.z;
            out_hidden[4 * t + 3] = hn.w;
        }
        __syncthreads();
    }

    // ---- S7: logits = W_o·h_new + b_o + fused exp-sum.
    //      Statically-unrolled double buffer: next row's 8 LDG.128 are in
    //      flight during the current row's dot + shuffle reduction, keeping
    //      DRAM duty near 100% (buffers alternate by code position, no
    //      predicated selects). ----
    {
        float esum = 0.f;
        float4 b0[8], b1[8];
        int v = gw;
        if (v < V) {
            const float4* w4 = reinterpret_cast<const float4*>(W_o + (size_t)v * H);
            #pragma unroll
            for (int k = 0; k < 8; k++) b0[k] = w4[lane + 32 * k];
        }
        while (v < V) {
            // --- phase A: b0 is current, prefetch into b1 ---
            int vn = v + NWARPS;
            if (vn < V) {
                const float4* w4 = reinterpret_cast<const float4*>(W_o + (size_t)vn * H);
                #pragma unroll
                for (int k = 0; k < 8; k++) b1[k] = w4[lane + 32 * k];
            }
            {
                float a0 = 0.f, a1 = 0.f;
                #pragma unroll
                for (int k = 0; k < 8; k += 2) {
                    a0 += dot4(b0[k],     sh[lane + 32 * k]);
                    a1 += dot4(b0[k + 1], sh[lane + 32 * (k + 1)]);
                }
                float d = warp_sum(a0 + a1);
                if (lane == 0) {
                    float lg = d + b_o[v];
                    out_logits[v] = lg;
                    esum += expf(lg);
                }
            }
            v = vn;
            if (v >= V) break;
            // --- phase B: b1 is current, prefetch into b0 ---
            vn = v + NWARPS;
            if (vn < V) {
                const float4* w4 = reinterpret_cast<const float4*>(W_o + (size_t)vn * H);
                #pragma unroll
                for (int k = 0; k < 8; k++) b0[k] = w4[lane + 32 * k];
            }
            {
                float a0 = 0.f, a1 = 0.f;
                #pragma unroll
                for (int k = 0; k < 8; k += 2) {
                    a0 += dot4(b1[k],     sh[lane + 32 * k]);
                    a1 += dot4(b1[k + 1], sh[lane + 32 * (k + 1)]);
                }
                float d = warp_sum(a0 + a1);
                if (lane == 0) {
                    float lg = d + b_o[v];
                    out_logits[v] = lg;
                    esum += expf(lg);
                }
            }
            v = vn;
        }
        if (lane == 0) atomicAdd(&g_sum, esum);
    }
    full_bar();

    // ---- S8: out[v] -= log(sum_exp) ----
    {
        float lse = logf(g_sum);
        for (int v = gt; v < V; v += NTHREADS) out_logits[v] -= lse;
    }
}

// ---------------- launch ----------------
extern "C" void kernel_launch(void* const* d_in, const int* in_sizes, int n_in,
                              void* d_out, int out_size) {
    const int*   y_i   = (const int*)  d_in[0];
    const float* h_i   = (const float*)d_in[1];
    const float* cnn_a = (const float*)d_in[2];
    const float* cnn_c = (const float*)d_in[3];
    const float* emb   = (const float*)d_in[4];
    const float* W_t   = (const float*)d_in[5];
    const float* b_t   = (const float*)d_in[6];
    const float* W_ih  = (const float*)d_in[7];
    const float* W_hh  = (const float*)d_in[8];
    const float* b_ih  = (const float*)d_in[9];
    const float* b_hh  = (const float*)d_in[10];
    const float* W_o   = (const float*)d_in[11];
    const float* b_o   = (const float*)d_in[12];

    const int V = in_sizes[11] / H;           // 50257
    float* out        = (float*)d_out;
    float* out_logits = out;
    float* out_hidden = out + (out_size - H);

    fused_decoder<<<NB, TPB>>>(y_i, h_i, cnn_a, cnn_c, emb, W_t, b_t,
                               W_ih, W_hh, b_ih, b_hh, W_o, b_o,
                               out_logits, out_hidden, V);
}